// round 8
// baseline (speedup 1.0000x reference)
#include <cuda_runtime.h>
#include <cuda.h>
#include <cstdint>
#include <dlfcn.h>

// ============================================================================
// out = x @ (W + 2*B@A)^T ; x:[8192,4096] f32, W:[4096,4096] f32
// R8 = R7 (1089.9us, rel_err 8.9e-5) +
//   1) merged quant kernel (x rows + w rows in one grid -> concurrent, DRAM-bound)
//   2) IMMA pass reordering (16-instr accumulator reuse distance, no RAW stalls)
//   3) 5-stage TMA pipeline.
// Scheme: x ~ sx*(Xhi + Xlo/254), w ~ sw*(Whi + Wlo/254),
//         out = sx*sw*( Xhi.Whi + (Xhi.Wlo + Xlo.Whi)/254 )  [lo.lo dropped]
// ============================================================================

static constexpr int M_ALL = 8192;
static constexpr int N_ALL = 4096;
static constexpr int K_ALL = 4096;
static constexpr int MT = 128;
static constexpr int NT = 128;
static constexpr int KC = 64;                  // K elements per stage
static constexpr int STAGES = 5;
static constexpr int KITERS = K_ALL / KC;      // 64
static constexpr int ROWB = 128;               // bytes per tile row (64 hi + 64 lo)
static constexpr int A_BYTES = MT * ROWB;      // 16384
static constexpr int B_BYTES = NT * ROWB;      // 16384
static constexpr int STAGE_BYTES = A_BYTES + B_BYTES;            // 32768
static constexpr int SMEM_TILE0 = 1024;
static constexpr int SMEM_TOTAL = SMEM_TILE0 + STAGES * STAGE_BYTES; // 164864

static constexpr int MB_FULL = 0;   // 5 x 8B
static constexpr int MB_EMPTY = 64; // 5 x 8B

// Scratch (static device globals; no allocation)
__device__ __align__(1024) char  g_xq[(size_t)M_ALL * 2 * K_ALL]; // 64 MB
__device__ __align__(1024) char  g_wq[(size_t)N_ALL * 2 * K_ALL]; // 32 MB
__device__ __align__(1024) float g_sx[M_ALL];
__device__ __align__(1024) float g_sw[N_ALL];

// ---------------------------------------------------------------------------
__device__ __forceinline__ uint32_t smem_u32(const void* p) {
    uint32_t a;
    asm("{ .reg .u64 t; cvta.to.shared.u64 t, %1; cvt.u32.u64 %0, t; }" : "=r"(a) : "l"(p));
    return a;
}
__device__ __forceinline__ uint32_t elect_one() {
    uint32_t p;
    asm volatile("{\n\t.reg .pred p;\n\telect.sync _|p, 0xFFFFFFFF;\n\tselp.b32 %0, 1, 0, p;\n\t}" : "=r"(p));
    return p;
}
__device__ __forceinline__ uint32_t lds32(uint32_t a) {
    uint32_t v;
    asm volatile("ld.shared.b32 %0, [%1];" : "=r"(v) : "r"(a));
    return v;
}

#define MBARRIER_INIT(addr, cnt) \
    asm volatile("mbarrier.init.shared.b64 [%0], %1;" :: "r"((uint32_t)(addr)), "r"((uint32_t)(cnt)) : "memory")
#define MBARRIER_EXPECT_TX(addr, bytes) \
    asm volatile("mbarrier.arrive.expect_tx.shared.b64 _, [%0], %1;" :: "r"((uint32_t)(addr)), "r"((uint32_t)(bytes)) : "memory")
#define MBARRIER_ARRIVE(addr) \
    asm volatile("mbarrier.arrive.shared.b64 _, [%0];" :: "r"((uint32_t)(addr)) : "memory")

#define MBARRIER_WAIT_PARITY(mbar_smem_addr, phase_parity) do { \
    uint32_t _mbar = (uint32_t)(mbar_smem_addr); \
    uint32_t _parity = (uint32_t)(phase_parity); \
    uint32_t _done; \
    asm volatile( \
        "{\n\t.reg .pred p;\n\t" \
        "mbarrier.try_wait.parity.acquire.cta.shared::cta.b64 p, [%1], %2;\n\t" \
        "selp.b32 %0, 1, 0, p;\n\t}" \
        : "=r"(_done) : "r"(_mbar), "r"(_parity) : "memory"); \
    if (!_done) { \
        asm volatile( \
            "{\n\t.reg .pred P1;\n\t" \
            "WAIT_LOOP_%=:\n\t" \
            "mbarrier.try_wait.parity.acquire.cta.shared::cta.b64 P1, [%0], %1, 0x989680;\n\t" \
            "@P1 bra.uni WAIT_DONE_%=;\n\t" \
            "bra.uni WAIT_LOOP_%=;\n\t" \
            "WAIT_DONE_%=:\n\t}" \
            :: "r"(_mbar), "r"(_parity) : "memory"); \
    } \
} while (0)

__device__ __forceinline__ void tma_load_2d(uint32_t smem_addr, const CUtensorMap* tm,
                                            int cx, int cy, uint32_t mbar) {
    asm volatile(
        "cp.async.bulk.tensor.2d.shared::cta.global.tile.mbarrier::complete_tx::bytes "
        "[%0], [%1, {%2, %3}], [%4];"
        :: "r"(smem_addr), "l"(tm), "r"(cx), "r"(cy), "r"(mbar) : "memory");
}

__device__ __forceinline__ void imma(int* d, const uint32_t* a, uint32_t b0, uint32_t b1) {
    asm("mma.sync.aligned.m16n8k32.row.col.s32.s8.s8.s32 "
        "{%0,%1,%2,%3}, {%4,%5,%6,%7}, {%8,%9}, {%0,%1,%2,%3};"
        : "+r"(d[0]), "+r"(d[1]), "+r"(d[2]), "+r"(d[3])
        : "r"(a[0]), "r"(a[1]), "r"(a[2]), "r"(a[3]), "r"(b0), "r"(b1));
}

// ---------------------------------------------------------------------------
// Merged quant kernel: blocks [0, M_ALL) quantize x rows; blocks [M_ALL,
// M_ALL+N_ALL) fold lora into W row and quantize. One row per block.
// Per row: s = max|row|/127; hi = rint(v), lo = rint((v-hi)*254) where
// v = row/s. Layout: byte k -> (k/64)*128 + (k%64) [hi] / +64 [lo].
// ---------------------------------------------------------------------------
__global__ void __launch_bounds__(256) quant_xw(const float* __restrict__ x,
                                                const float* __restrict__ W,
                                                const float* __restrict__ lA,
                                                const float* __restrict__ lB) {
    __shared__ float srow[4096];
    __shared__ float swarp[8];
    __shared__ float sscale;
    __shared__ float sB[16];
    const int bid = blockIdx.x, tid = threadIdx.x;
    const int lane = tid & 31, warp = tid >> 5;
    const bool is_x = bid < M_ALL;
    const int row = is_x ? bid : bid - M_ALL;

    float4* sr4 = reinterpret_cast<float4*>(srow);
    float m = 0.f;

    if (is_x) {
        const float4* xr = reinterpret_cast<const float4*>(x + (size_t)row * K_ALL);
        #pragma unroll 1
        for (int i = tid; i < 1024; i += 256) {
            float4 v = xr[i];
            sr4[i] = v;
            m = fmaxf(m, fmaxf(fmaxf(fabsf(v.x), fabsf(v.y)), fmaxf(fabsf(v.z), fabsf(v.w))));
        }
    } else {
        if (tid < 16) sB[tid] = 2.0f * lB[row * 16 + tid];
        __syncthreads();
        const float4* W4 = reinterpret_cast<const float4*>(W + (size_t)row * K_ALL);
        #pragma unroll 1
        for (int i = tid; i < 1024; i += 256) {
            float4 acc = W4[i];
            #pragma unroll
            for (int r = 0; r < 16; r++) {
                float4 a = reinterpret_cast<const float4*>(lA + (size_t)r * K_ALL)[i];
                acc.x = fmaf(sB[r], a.x, acc.x);
                acc.y = fmaf(sB[r], a.y, acc.y);
                acc.z = fmaf(sB[r], a.z, acc.z);
                acc.w = fmaf(sB[r], a.w, acc.w);
            }
            sr4[i] = acc;
            m = fmaxf(m, fmaxf(fmaxf(fabsf(acc.x), fabsf(acc.y)), fmaxf(fabsf(acc.z), fabsf(acc.w))));
        }
    }

    // warp reduce then block reduce (2 syncs)
    #pragma unroll
    for (int o = 16; o > 0; o >>= 1) m = fmaxf(m, __shfl_xor_sync(0xFFFFFFFFu, m, o));
    if (lane == 0) swarp[warp] = m;
    __syncthreads();
    if (warp == 0) {
        float v = (lane < 8) ? swarp[lane] : 0.f;
        #pragma unroll
        for (int o = 4; o > 0; o >>= 1) v = fmaxf(v, __shfl_xor_sync(0xFFFFFFFFu, v, o));
        if (lane == 0) {
            const float s = fmaxf(v, 1e-30f);
            sscale = 127.0f / s;
            if (is_x) g_sx[row] = s * (1.0f / 127.0f);
            else      g_sw[row] = s * (1.0f / 127.0f);
        }
    }
    __syncthreads();
    const float inv = sscale;

    char* orow = (is_x ? g_xq : g_wq) + (size_t)row * (2 * K_ALL);
    #pragma unroll 1
    for (int i = tid; i < 1024; i += 256) {
        const int k = i * 4;
        char4 hi, lo;
        #pragma unroll
        for (int j = 0; j < 4; j++) {
            float v = srow[k + j] * inv;
            int h = __float2int_rn(v);
            int l = __float2int_rn((v - (float)h) * 254.0f);
            reinterpret_cast<char*>(&hi)[j] = (char)h;
            reinterpret_cast<char*>(&lo)[j] = (char)l;
        }
        const int off = ((k >> 6) << 7) + (k & 63);
        *reinterpret_cast<char4*>(orow + off) = hi;
        *reinterpret_cast<char4*>(orow + off + 64) = lo;
    }
}

// ---------------------------------------------------------------------------
// GEMM: smem tile rows of 128B (chunks 0-3 = hi 64B, 4-7 = lo 64B), TMA SW128:
// 16B chunk j of row r lands at j ^ (r&7). warps 0-7 compute (2x4, 64x32),
// warp 8 = TMA producer.
// ---------------------------------------------------------------------------
__global__ void __launch_bounds__(288, 1)
gemm_s8(const __grid_constant__ CUtensorMap tmA,
        const __grid_constant__ CUtensorMap tmB,
        float* __restrict__ out) {
    extern __shared__ char smem[];
    uint32_t sb = smem_u32(smem);
    const int tid = threadIdx.x, wid = tid >> 5, lane = tid & 31;
    const int mtile = blockIdx.y, ntile = blockIdx.x;

    if (tid == 0) {
        #pragma unroll
        for (int s = 0; s < STAGES; s++) {
            MBARRIER_INIT(sb + MB_FULL + 8 * s, 1);
            MBARRIER_INIT(sb + MB_EMPTY + 8 * s, 8);
        }
        asm volatile("fence.proxy.async.shared::cta;" ::: "memory");
    }
    __syncthreads();

    if (wid == 8) {
        // ---------------- producer ----------------
        if (elect_one()) {
            int st = 0, ph = 1;
            for (int k = 0; k < KITERS; k++) {
                MBARRIER_WAIT_PARITY(sb + MB_EMPTY + 8 * st, ph);
                MBARRIER_EXPECT_TX(sb + MB_FULL + 8 * st, STAGE_BYTES);
                uint32_t abase = sb + SMEM_TILE0 + st * STAGE_BYTES;
                tma_load_2d(abase, &tmA, k * ROWB, mtile * MT, sb + MB_FULL + 8 * st);
                tma_load_2d(abase + A_BYTES, &tmB, k * ROWB, ntile * NT, sb + MB_FULL + 8 * st);
                if (++st == STAGES) { st = 0; ph ^= 1; }
            }
        }
        return;
    }

    // ---------------- compute warps: 2x4, warp tile 64x32 ----------------
    const int mw = (wid >> 2) * 64;   // 0 / 64
    const int nw = (wid & 3) * 32;    // 0,32,64,96
    const int g = lane >> 2;          // 0..7
    const int q = lane & 3;           // 0..3
    const uint32_t q4 = (uint32_t)(q << 2);

    int acc1[4][4][4], acc2[4][4][4];
    #pragma unroll
    for (int tm = 0; tm < 4; tm++)
        #pragma unroll
        for (int tn = 0; tn < 4; tn++)
            #pragma unroll
            for (int r = 0; r < 4; r++) { acc1[tm][tn][r] = 0; acc2[tm][tn][r] = 0; }

    int st = 0, ph = 0;
    for (int k = 0; k < KITERS; k++) {
        if (elect_one()) MBARRIER_WAIT_PARITY(sb + MB_FULL + 8 * st, ph);
        __syncwarp();

        const uint32_t sa = sb + SMEM_TILE0 + st * STAGE_BYTES;
        const uint32_t aRow = sa + (mw + g) * ROWB;
        const uint32_t bRow = sa + A_BYTES + (nw + g) * ROWB;

        #pragma unroll
        for (int s = 0; s < 2; s++) {  // two k32 sub-chunks
            const uint32_t cH0 = (uint32_t)(((2 * s + 0) ^ g) << 4);
            const uint32_t cH1 = (uint32_t)(((2 * s + 1) ^ g) << 4);
            const uint32_t cL0 = (uint32_t)(((2 * s + 4) ^ g) << 4);
            const uint32_t cL1 = (uint32_t)(((2 * s + 5) ^ g) << 4);

            uint32_t ah[4][4], al[4][4];
            #pragma unroll
            for (int tm = 0; tm < 4; tm++) {
                const uint32_t base = aRow + tm * 2048;     // 16 rows * 128B
                ah[tm][0] = lds32(base + cH0 + q4);
                ah[tm][1] = lds32(base + 1024 + cH0 + q4);  // +8 rows
                ah[tm][2] = lds32(base + cH1 + q4);
                ah[tm][3] = lds32(base + 1024 + cH1 + q4);
                al[tm][0] = lds32(base + cL0 + q4);
                al[tm][1] = lds32(base + 1024 + cL0 + q4);
                al[tm][2] = lds32(base + cL1 + q4);
                al[tm][3] = lds32(base + 1024 + cL1 + q4);
            }
            uint32_t bh[4][2], bl[4][2];
            #pragma unroll
            for (int tn = 0; tn < 4; tn++) {
                const uint32_t base = bRow + tn * 1024;     // 8 rows * 128B
                bh[tn][0] = lds32(base + cH0 + q4);
                bh[tn][1] = lds32(base + cH1 + q4);
                bl[tn][0] = lds32(base + cL0 + q4);
                bl[tn][1] = lds32(base + cL1 + q4);
            }
            // pass 1: hi.hi -> acc1 (16 independent IMMAs)
            #pragma unroll
            for (int tm = 0; tm < 4; tm++)
                #pragma unroll
                for (int tn = 0; tn < 4; tn++)
                    imma(acc1[tm][tn], ah[tm], bh[tn][0], bh[tn][1]);
            // pass 2: hi.lo -> acc2 (16 independent IMMAs)
            #pragma unroll
            for (int tm = 0; tm < 4; tm++)
                #pragma unroll
                for (int tn = 0; tn < 4; tn++)
                    imma(acc2[tm][tn], ah[tm], bl[tn][0], bl[tn][1]);
            // pass 3: lo.hi -> acc2 (reuse distance 16 from pass 2)
            #pragma unroll
            for (int tm = 0; tm < 4; tm++)
                #pragma unroll
                for (int tn = 0; tn < 4; tn++)
                    imma(acc2[tm][tn], al[tm], bh[tn][0], bh[tn][1]);
        }

        if (elect_one()) MBARRIER_ARRIVE(sb + MB_EMPTY + 8 * st);
        if (++st == STAGES) { st = 0; ph ^= 1; }
    }

    // ---------------- epilogue: out = sx*sw*(acc1 + acc2/254) ----------------
    const float INV254 = 1.0f / 254.0f;
    #pragma unroll
    for (int tm = 0; tm < 4; tm++) {
        const int r0 = mtile * MT + mw + tm * 16 + g;
        const int r1 = r0 + 8;
        const float sx0 = g_sx[r0], sx1 = g_sx[r1];
        #pragma unroll
        for (int tn = 0; tn < 4; tn++) {
            const int c = ntile * NT + nw + tn * 8 + 2 * q;
            const float sw0 = g_sw[c], sw1 = g_sw[c + 1];
            float v00 = sx0 * sw0 * ((float)acc1[tm][tn][0] + (float)acc2[tm][tn][0] * INV254);
            float v01 = sx0 * sw1 * ((float)acc1[tm][tn][1] + (float)acc2[tm][tn][1] * INV254);
            float v10 = sx1 * sw0 * ((float)acc1[tm][tn][2] + (float)acc2[tm][tn][2] * INV254);
            float v11 = sx1 * sw1 * ((float)acc1[tm][tn][3] + (float)acc2[tm][tn][3] * INV254);
            *reinterpret_cast<float2*>(out + (size_t)r0 * N_ALL + c) = make_float2(v00, v01);
            *reinterpret_cast<float2*>(out + (size_t)r1 * N_ALL + c) = make_float2(v10, v11);
        }
    }
}

// ---------------------------------------------------------------------------
typedef CUresult (*EncodeFn)(CUtensorMap*, CUtensorMapDataType, cuuint32_t, void*,
                             const cuuint64_t*, const cuuint64_t*, const cuuint32_t*,
                             const cuuint32_t*, CUtensorMapInterleave, CUtensorMapSwizzle,
                             CUtensorMapL2promotion, CUtensorMapFloatOOBfill);

extern "C" void kernel_launch(void* const* d_in, const int* in_sizes, int n_in,
                              void* d_out, int out_size) {
    const float* x  = (const float*)d_in[0];
    const float* W  = (const float*)d_in[1];
    const float* lA = (const float*)d_in[2];
    const float* lB = (const float*)d_in[3];
    float* out = (float*)d_out;

    void* xq = nullptr;
    void* wq = nullptr;
    cudaGetSymbolAddress(&xq, g_xq);
    cudaGetSymbolAddress(&wq, g_wq);

    void* h = dlopen("libcuda.so.1", RTLD_LAZY | RTLD_GLOBAL);
    if (!h) h = dlopen("libcuda.so", RTLD_LAZY | RTLD_GLOBAL);
    EncodeFn enc = h ? (EncodeFn)dlsym(h, "cuTensorMapEncodeTiled") : nullptr;
    if (!enc || !xq || !wq) return;

    CUtensorMap tmA{}, tmB{};
    {
        cuuint64_t dims[2] = {(cuuint64_t)(2 * K_ALL), (cuuint64_t)M_ALL};
        cuuint64_t str[1]  = {(cuuint64_t)(2 * K_ALL)};
        cuuint32_t box[2]  = {(cuuint32_t)ROWB, (cuuint32_t)MT};
        cuuint32_t es[2]   = {1, 1};
        enc(&tmA, CU_TENSOR_MAP_DATA_TYPE_UINT8, 2, xq, dims, str, box, es,
            CU_TENSOR_MAP_INTERLEAVE_NONE, CU_TENSOR_MAP_SWIZZLE_128B,
            CU_TENSOR_MAP_L2_PROMOTION_L2_128B, CU_TENSOR_MAP_FLOAT_OOB_FILL_NONE);
    }
    {
        cuuint64_t dims[2] = {(cuuint64_t)(2 * K_ALL), (cuuint64_t)N_ALL};
        cuuint64_t str[1]  = {(cuuint64_t)(2 * K_ALL)};
        cuuint32_t box[2]  = {(cuuint32_t)ROWB, (cuuint32_t)NT};
        cuuint32_t es[2]   = {1, 1};
        enc(&tmB, CU_TENSOR_MAP_DATA_TYPE_UINT8, 2, wq, dims, str, box, es,
            CU_TENSOR_MAP_INTERLEAVE_NONE, CU_TENSOR_MAP_SWIZZLE_128B,
            CU_TENSOR_MAP_L2_PROMOTION_L2_128B, CU_TENSOR_MAP_FLOAT_OOB_FILL_NONE);
    }

    cudaFuncSetAttribute(gemm_s8, cudaFuncAttributeMaxDynamicSharedMemorySize, SMEM_TOTAL);

    quant_xw<<<M_ALL + N_ALL, 256>>>(x, W, lA, lB);

    dim3 grid(N_ALL / NT, M_ALL / MT); // (32, 64)
    gemm_s8<<<grid, 288, SMEM_TOTAL>>>(tmA, tmB, out);
}

// round 9
// speedup vs baseline: 1.1158x; 1.1158x over previous
#include <cuda_runtime.h>
#include <cuda.h>
#include <cstdint>
#include <dlfcn.h>

// ============================================================================
// out = x @ (W + 2*B@A)^T ; x:[8192,4096] f32, W:[4096,4096] f32
// R9 = R7 GEMM byte-exact (1089.9us, rel_err 8.9e-5) + ONE change:
//      merged, load-balanced quant kernel (2 x-rows : 1 w-row interleave).
// Scheme: x ~ sx*(Xhi + Xlo/254), w ~ sw*(Whi + Wlo/254),
//         out = sx*sw*( Xhi.Whi + (Xhi.Wlo + Xlo.Whi)/254 )  [lo.lo dropped]
// ============================================================================

static constexpr int M_ALL = 8192;
static constexpr int N_ALL = 4096;
static constexpr int K_ALL = 4096;
static constexpr int MT = 128;
static constexpr int NT = 128;
static constexpr int KC = 64;                  // K elements per stage
static constexpr int STAGES = 4;
static constexpr int KITERS = K_ALL / KC;      // 64
static constexpr int ROWB = 128;               // bytes per tile row (64 hi + 64 lo)
static constexpr int A_BYTES = MT * ROWB;      // 16384
static constexpr int B_BYTES = NT * ROWB;      // 16384
static constexpr int STAGE_BYTES = A_BYTES + B_BYTES;            // 32768
static constexpr int SMEM_TILE0 = 1024;
static constexpr int SMEM_TOTAL = SMEM_TILE0 + STAGES * STAGE_BYTES; // 132096

static constexpr int MB_FULL = 0;
static constexpr int MB_EMPTY = 64;

// Scratch (static device globals; no allocation)
__device__ __align__(1024) char  g_xq[(size_t)M_ALL * 2 * K_ALL]; // 64 MB
__device__ __align__(1024) char  g_wq[(size_t)N_ALL * 2 * K_ALL]; // 32 MB
__device__ __align__(1024) float g_sx[M_ALL];
__device__ __align__(1024) float g_sw[N_ALL];

// ---------------------------------------------------------------------------
__device__ __forceinline__ uint32_t smem_u32(const void* p) {
    uint32_t a;
    asm("{ .reg .u64 t; cvta.to.shared.u64 t, %1; cvt.u32.u64 %0, t; }" : "=r"(a) : "l"(p));
    return a;
}
__device__ __forceinline__ uint32_t elect_one() {
    uint32_t p;
    asm volatile("{\n\t.reg .pred p;\n\telect.sync _|p, 0xFFFFFFFF;\n\tselp.b32 %0, 1, 0, p;\n\t}" : "=r"(p));
    return p;
}
__device__ __forceinline__ uint32_t lds32(uint32_t a) {
    uint32_t v;
    asm volatile("ld.shared.b32 %0, [%1];" : "=r"(v) : "r"(a));
    return v;
}

#define MBARRIER_INIT(addr, cnt) \
    asm volatile("mbarrier.init.shared.b64 [%0], %1;" :: "r"((uint32_t)(addr)), "r"((uint32_t)(cnt)) : "memory")
#define MBARRIER_EXPECT_TX(addr, bytes) \
    asm volatile("mbarrier.arrive.expect_tx.shared.b64 _, [%0], %1;" :: "r"((uint32_t)(addr)), "r"((uint32_t)(bytes)) : "memory")
#define MBARRIER_ARRIVE(addr) \
    asm volatile("mbarrier.arrive.shared.b64 _, [%0];" :: "r"((uint32_t)(addr)) : "memory")

#define MBARRIER_WAIT_PARITY(mbar_smem_addr, phase_parity) do { \
    uint32_t _mbar = (uint32_t)(mbar_smem_addr); \
    uint32_t _parity = (uint32_t)(phase_parity); \
    uint32_t _done; \
    asm volatile( \
        "{\n\t.reg .pred p;\n\t" \
        "mbarrier.try_wait.parity.acquire.cta.shared::cta.b64 p, [%1], %2;\n\t" \
        "selp.b32 %0, 1, 0, p;\n\t}" \
        : "=r"(_done) : "r"(_mbar), "r"(_parity) : "memory"); \
    if (!_done) { \
        asm volatile( \
            "{\n\t.reg .pred P1;\n\t" \
            "WAIT_LOOP_%=:\n\t" \
            "mbarrier.try_wait.parity.acquire.cta.shared::cta.b64 P1, [%0], %1, 0x989680;\n\t" \
            "@P1 bra.uni WAIT_DONE_%=;\n\t" \
            "bra.uni WAIT_LOOP_%=;\n\t" \
            "WAIT_DONE_%=:\n\t}" \
            :: "r"(_mbar), "r"(_parity) : "memory"); \
    } \
} while (0)

__device__ __forceinline__ void tma_load_2d(uint32_t smem_addr, const CUtensorMap* tm,
                                            int cx, int cy, uint32_t mbar) {
    asm volatile(
        "cp.async.bulk.tensor.2d.shared::cta.global.tile.mbarrier::complete_tx::bytes "
        "[%0], [%1, {%2, %3}], [%4];"
        :: "r"(smem_addr), "l"(tm), "r"(cx), "r"(cy), "r"(mbar) : "memory");
}

__device__ __forceinline__ void imma(int* d, const uint32_t* a, uint32_t b0, uint32_t b1) {
    asm("mma.sync.aligned.m16n8k32.row.col.s32.s8.s8.s32 "
        "{%0,%1,%2,%3}, {%4,%5,%6,%7}, {%8,%9}, {%0,%1,%2,%3};"
        : "+r"(d[0]), "+r"(d[1]), "+r"(d[2]), "+r"(d[3])
        : "r"(a[0]), "r"(a[1]), "r"(a[2]), "r"(a[3]), "r"(b0), "r"(b1));
}

// ---------------------------------------------------------------------------
// Merged quant kernel, load-balanced: every 3 consecutive blocks handle
// 2 x-rows + 1 w-row (w-rows cost ~4x an x-row; interleave avoids a w tail).
// Per row: s = max|row|/127; v = row*127/s; hi = rint(v); lo = rint((v-hi)*254)
// Layout: byte k -> (k/64)*128 + (k%64) [hi] / +64 [lo].
// ---------------------------------------------------------------------------
__global__ void __launch_bounds__(256) quant_xw(const float* __restrict__ x,
                                                const float* __restrict__ W,
                                                const float* __restrict__ lA,
                                                const float* __restrict__ lB) {
    __shared__ float srow[4096];
    __shared__ float swarp[8];
    __shared__ float sscale;
    __shared__ float sB[16];
    const int bid = blockIdx.x, tid = threadIdx.x;
    const int lane = tid & 31, warp = tid >> 5;
    const int j = bid / 3, r3 = bid - 3 * j;
    const bool is_x = (r3 < 2);
    const int row = is_x ? (2 * j + r3) : j;

    float4* sr4 = reinterpret_cast<float4*>(srow);
    float m = 0.f;

    if (is_x) {
        const float4* xr = reinterpret_cast<const float4*>(x + (size_t)row * K_ALL);
        #pragma unroll 1
        for (int i = tid; i < 1024; i += 256) {
            float4 v = xr[i];
            sr4[i] = v;
            m = fmaxf(m, fmaxf(fmaxf(fabsf(v.x), fabsf(v.y)), fmaxf(fabsf(v.z), fabsf(v.w))));
        }
    } else {
        if (tid < 16) sB[tid] = 2.0f * lB[row * 16 + tid];
        __syncthreads();
        const float4* W4 = reinterpret_cast<const float4*>(W + (size_t)row * K_ALL);
        #pragma unroll 1
        for (int i = tid; i < 1024; i += 256) {
            float4 acc = W4[i];
            #pragma unroll
            for (int r = 0; r < 16; r++) {
                float4 a = reinterpret_cast<const float4*>(lA + (size_t)r * K_ALL)[i];
                acc.x = fmaf(sB[r], a.x, acc.x);
                acc.y = fmaf(sB[r], a.y, acc.y);
                acc.z = fmaf(sB[r], a.z, acc.z);
                acc.w = fmaf(sB[r], a.w, acc.w);
            }
            sr4[i] = acc;
            m = fmaxf(m, fmaxf(fmaxf(fabsf(acc.x), fabsf(acc.y)), fmaxf(fabsf(acc.z), fabsf(acc.w))));
        }
    }

    // warp reduce then block reduce
    #pragma unroll
    for (int o = 16; o > 0; o >>= 1) m = fmaxf(m, __shfl_xor_sync(0xFFFFFFFFu, m, o));
    if (lane == 0) swarp[warp] = m;
    __syncthreads();
    if (warp == 0) {
        float v = (lane < 8) ? swarp[lane] : 0.f;
        #pragma unroll
        for (int o = 4; o > 0; o >>= 1) v = fmaxf(v, __shfl_xor_sync(0xFFFFFFFFu, v, o));
        if (lane == 0) {
            const float s = fmaxf(v, 1e-30f);
            sscale = 127.0f / s;
            if (is_x) g_sx[row] = s * (1.0f / 127.0f);
            else      g_sw[row] = s * (1.0f / 127.0f);
        }
    }
    __syncthreads();
    const float inv = sscale;

    char* orow = (is_x ? g_xq : g_wq) + (size_t)row * (2 * K_ALL);
    #pragma unroll 1
    for (int i = tid; i < 1024; i += 256) {
        const int k = i * 4;
        char4 hi, lo;
        #pragma unroll
        for (int jj = 0; jj < 4; jj++) {
            float v = srow[k + jj] * inv;
            int h = __float2int_rn(v);
            int l = __float2int_rn((v - (float)h) * 254.0f);
            reinterpret_cast<char*>(&hi)[jj] = (char)h;
            reinterpret_cast<char*>(&lo)[jj] = (char)l;
        }
        const int off = ((k >> 6) << 7) + (k & 63);
        *reinterpret_cast<char4*>(orow + off) = hi;
        *reinterpret_cast<char4*>(orow + off + 64) = lo;
    }
}

// ---------------------------------------------------------------------------
// GEMM (byte-exact R7): smem tile rows of 128B (chunks 0-3 hi, 4-7 lo),
// TMA SW128: 16B chunk j of row r lands at j ^ (r&7).
// warps 0-7 compute (2x4, warp tile 64x32), warp 8 = TMA producer.
// ---------------------------------------------------------------------------
__global__ void __launch_bounds__(288, 1)
gemm_s8(const __grid_constant__ CUtensorMap tmA,
        const __grid_constant__ CUtensorMap tmB,
        float* __restrict__ out) {
    extern __shared__ char smem[];
    uint32_t sb = smem_u32(smem);
    const int tid = threadIdx.x, wid = tid >> 5, lane = tid & 31;
    const int mtile = blockIdx.y, ntile = blockIdx.x;

    if (tid == 0) {
        #pragma unroll
        for (int s = 0; s < STAGES; s++) {
            MBARRIER_INIT(sb + MB_FULL + 8 * s, 1);
            MBARRIER_INIT(sb + MB_EMPTY + 8 * s, 8);
        }
        asm volatile("fence.proxy.async.shared::cta;" ::: "memory");
    }
    __syncthreads();

    if (wid == 8) {
        // ---------------- producer ----------------
        if (elect_one()) {
            int st = 0, ph = 1;
            for (int k = 0; k < KITERS; k++) {
                MBARRIER_WAIT_PARITY(sb + MB_EMPTY + 8 * st, ph);
                MBARRIER_EXPECT_TX(sb + MB_FULL + 8 * st, STAGE_BYTES);
                uint32_t abase = sb + SMEM_TILE0 + st * STAGE_BYTES;
                tma_load_2d(abase, &tmA, k * ROWB, mtile * MT, sb + MB_FULL + 8 * st);
                tma_load_2d(abase + A_BYTES, &tmB, k * ROWB, ntile * NT, sb + MB_FULL + 8 * st);
                if (++st == STAGES) { st = 0; ph ^= 1; }
            }
        }
        return;
    }

    // ---------------- compute warps: 2x4, warp tile 64x32 ----------------
    const int mw = (wid >> 2) * 64;   // 0 / 64
    const int nw = (wid & 3) * 32;    // 0,32,64,96
    const int g = lane >> 2;          // 0..7
    const int q = lane & 3;           // 0..3
    const uint32_t q4 = (uint32_t)(q << 2);

    int acc1[4][4][4], acc2[4][4][4];
    #pragma unroll
    for (int tm = 0; tm < 4; tm++)
        #pragma unroll
        for (int tn = 0; tn < 4; tn++)
            #pragma unroll
            for (int r = 0; r < 4; r++) { acc1[tm][tn][r] = 0; acc2[tm][tn][r] = 0; }

    int st = 0, ph = 0;
    for (int k = 0; k < KITERS; k++) {
        if (elect_one()) MBARRIER_WAIT_PARITY(sb + MB_FULL + 8 * st, ph);
        __syncwarp();

        const uint32_t sa = sb + SMEM_TILE0 + st * STAGE_BYTES;
        const uint32_t aRow = sa + (mw + g) * ROWB;
        const uint32_t bRow = sa + A_BYTES + (nw + g) * ROWB;

        #pragma unroll
        for (int s = 0; s < 2; s++) {  // two k32 sub-chunks
            const uint32_t cH0 = (uint32_t)(((2 * s + 0) ^ g) << 4);
            const uint32_t cH1 = (uint32_t)(((2 * s + 1) ^ g) << 4);
            const uint32_t cL0 = (uint32_t)(((2 * s + 4) ^ g) << 4);
            const uint32_t cL1 = (uint32_t)(((2 * s + 5) ^ g) << 4);

            uint32_t ah[4][4], al[4][4];
            #pragma unroll
            for (int tm = 0; tm < 4; tm++) {
                const uint32_t base = aRow + tm * 2048;     // 16 rows * 128B
                ah[tm][0] = lds32(base + cH0 + q4);
                ah[tm][1] = lds32(base + 1024 + cH0 + q4);  // +8 rows
                ah[tm][2] = lds32(base + cH1 + q4);
                ah[tm][3] = lds32(base + 1024 + cH1 + q4);
                al[tm][0] = lds32(base + cL0 + q4);
                al[tm][1] = lds32(base + 1024 + cL0 + q4);
                al[tm][2] = lds32(base + cL1 + q4);
                al[tm][3] = lds32(base + 1024 + cL1 + q4);
            }
            uint32_t bh[4][2], bl[4][2];
            #pragma unroll
            for (int tn = 0; tn < 4; tn++) {
                const uint32_t base = bRow + tn * 1024;     // 8 rows * 128B
                bh[tn][0] = lds32(base + cH0 + q4);
                bh[tn][1] = lds32(base + cH1 + q4);
                bl[tn][0] = lds32(base + cL0 + q4);
                bl[tn][1] = lds32(base + cL1 + q4);
            }
            #pragma unroll
            for (int tm = 0; tm < 4; tm++)
                #pragma unroll
                for (int tn = 0; tn < 4; tn++) {
                    imma(acc1[tm][tn], ah[tm], bh[tn][0], bh[tn][1]);
                    imma(acc2[tm][tn], ah[tm], bl[tn][0], bl[tn][1]);
                    imma(acc2[tm][tn], al[tm], bh[tn][0], bh[tn][1]);
                }
        }

        if (elect_one()) MBARRIER_ARRIVE(sb + MB_EMPTY + 8 * st);
        if (++st == STAGES) { st = 0; ph ^= 1; }
    }

    // ---------------- epilogue: out = sx*sw*(acc1 + acc2/254) ----------------
    const float INV254 = 1.0f / 254.0f;
    #pragma unroll
    for (int tm = 0; tm < 4; tm++) {
        const int r0 = mtile * MT + mw + tm * 16 + g;
        const int r1 = r0 + 8;
        const float sx0 = g_sx[r0], sx1 = g_sx[r1];
        #pragma unroll
        for (int tn = 0; tn < 4; tn++) {
            const int c = ntile * NT + nw + tn * 8 + 2 * q;
            const float sw0 = g_sw[c], sw1 = g_sw[c + 1];
            float v00 = sx0 * sw0 * ((float)acc1[tm][tn][0] + (float)acc2[tm][tn][0] * INV254);
            float v01 = sx0 * sw1 * ((float)acc1[tm][tn][1] + (float)acc2[tm][tn][1] * INV254);
            float v10 = sx1 * sw0 * ((float)acc1[tm][tn][2] + (float)acc2[tm][tn][2] * INV254);
            float v11 = sx1 * sw1 * ((float)acc1[tm][tn][3] + (float)acc2[tm][tn][3] * INV254);
            *reinterpret_cast<float2*>(out + (size_t)r0 * N_ALL + c) = make_float2(v00, v01);
            *reinterpret_cast<float2*>(out + (size_t)r1 * N_ALL + c) = make_float2(v10, v11);
        }
    }
}

// ---------------------------------------------------------------------------
typedef CUresult (*EncodeFn)(CUtensorMap*, CUtensorMapDataType, cuuint32_t, void*,
                             const cuuint64_t*, const cuuint64_t*, const cuuint32_t*,
                             const cuuint32_t*, CUtensorMapInterleave, CUtensorMapSwizzle,
                             CUtensorMapL2promotion, CUtensorMapFloatOOBfill);

extern "C" void kernel_launch(void* const* d_in, const int* in_sizes, int n_in,
                              void* d_out, int out_size) {
    const float* x  = (const float*)d_in[0];
    const float* W  = (const float*)d_in[1];
    const float* lA = (const float*)d_in[2];
    const float* lB = (const float*)d_in[3];
    float* out = (float*)d_out;

    void* xq = nullptr;
    void* wq = nullptr;
    cudaGetSymbolAddress(&xq, g_xq);
    cudaGetSymbolAddress(&wq, g_wq);

    void* h = dlopen("libcuda.so.1", RTLD_LAZY | RTLD_GLOBAL);
    if (!h) h = dlopen("libcuda.so", RTLD_LAZY | RTLD_GLOBAL);
    EncodeFn enc = h ? (EncodeFn)dlsym(h, "cuTensorMapEncodeTiled") : nullptr;
    if (!enc || !xq || !wq) return;

    CUtensorMap tmA{}, tmB{};
    {
        cuuint64_t dims[2] = {(cuuint64_t)(2 * K_ALL), (cuuint64_t)M_ALL};
        cuuint64_t str[1]  = {(cuuint64_t)(2 * K_ALL)};
        cuuint32_t box[2]  = {(cuuint32_t)ROWB, (cuuint32_t)MT};
        cuuint32_t es[2]   = {1, 1};
        enc(&tmA, CU_TENSOR_MAP_DATA_TYPE_UINT8, 2, xq, dims, str, box, es,
            CU_TENSOR_MAP_INTERLEAVE_NONE, CU_TENSOR_MAP_SWIZZLE_128B,
            CU_TENSOR_MAP_L2_PROMOTION_L2_128B, CU_TENSOR_MAP_FLOAT_OOB_FILL_NONE);
    }
    {
        cuuint64_t dims[2] = {(cuuint64_t)(2 * K_ALL), (cuuint64_t)N_ALL};
        cuuint64_t str[1]  = {(cuuint64_t)(2 * K_ALL)};
        cuuint32_t box[2]  = {(cuuint32_t)ROWB, (cuuint32_t)NT};
        cuuint32_t es[2]   = {1, 1};
        enc(&tmB, CU_TENSOR_MAP_DATA_TYPE_UINT8, 2, wq, dims, str, box, es,
            CU_TENSOR_MAP_INTERLEAVE_NONE, CU_TENSOR_MAP_SWIZZLE_128B,
            CU_TENSOR_MAP_L2_PROMOTION_L2_128B, CU_TENSOR_MAP_FLOAT_OOB_FILL_NONE);
    }

    cudaFuncSetAttribute(gemm_s8, cudaFuncAttributeMaxDynamicSharedMemorySize, SMEM_TOTAL);

    quant_xw<<<M_ALL + N_ALL, 256>>>(x, W, lA, lB);  // 12288 blocks: 3 -> 2 x-rows + 1 w-row

    dim3 grid(N_ALL / NT, M_ALL / MT); // (32, 64)
    gemm_s8<<<grid, 288, SMEM_TOTAL>>>(tmA, tmB, out);
}